// round 1
// baseline (speedup 1.0000x reference)
#include <cuda_runtime.h>

#define BATCH 32768
#define CI 14
#define NN 52
#define H1C 64
#define L 128
#define KFLAT (NN*L)   // 6656
#define CLS 2

// ---- scratch (device globals: no allocation allowed) ----
__device__ float g_y[(size_t)BATCH * KFLAT];   // y_pre  [B,52,128]
__device__ float g_f[(size_t)BATCH * H1C];     // f      [B,64]
__device__ float g_w01[L * CI];                // folded w1@w0  [128,14]
__device__ float g_b01[L];
__device__ float g_sum1[NN], g_sq1[NN], g_a1[NN], g_bb1[NN];
__device__ float g_sum2[H1C], g_sq2[H1C], g_a2[H1C], g_bb2[H1C];

// ---------------------------------------------------------------------------
// prep: fold the two linear GNN layers; zero stat accumulators
// ---------------------------------------------------------------------------
__global__ void prep_kernel(const float* __restrict__ w0, const float* __restrict__ b0,
                            const float* __restrict__ w1, const float* __restrict__ b1) {
    int t = threadIdx.x;
    if (t < NN)  { g_sum1[t] = 0.f; g_sq1[t] = 0.f; }
    if (t < H1C) { g_sum2[t] = 0.f; g_sq2[t] = 0.f; }
    for (int idx = t; idx < L * CI; idx += blockDim.x) {
        int j = idx / CI, k = idx % CI;
        float acc = 0.f;
        for (int i = 0; i < H1C; i++) acc += w1[j*H1C + i] * w0[i*CI + k];
        g_w01[idx] = acc;
    }
    if (t < L) {
        float acc = b1[t];
        for (int i = 0; i < H1C; i++) acc += w1[t*H1C + i] * b0[i];
        g_b01[t] = acc;
    }
}

// ---------------------------------------------------------------------------
// kernel A: per sample  h2 = relu(xt @ w01.T + b01)  [52,128]
//           y  = wc @ h2 + bc                        [52,128] -> g_y
//           accumulate per-channel sum / sumsq for BN1
// ---------------------------------------------------------------------------
__global__ void __launch_bounds__(256, 3) kernelA(const float* __restrict__ x,
                                                  const float* __restrict__ wc,
                                                  const float* __restrict__ bc) {
    __shared__ __align__(16) float s_w01t[CI][L];   // [k][j]
    __shared__ float s_b01[L];
    __shared__ __align__(16) float s_wcT[NN*NN];    // [k*52 + o]
    __shared__ float s_bc[NN];
    __shared__ float s_x[CI][NN];                   // [c][n]  (x natural layout)
    __shared__ __align__(16) float s_h2[NN][L];     // [n][l]
    __shared__ float s_red[2*NN];

    int t = threadIdx.x;
    for (int idx = t; idx < L*CI; idx += 256) { int j = idx / CI, k = idx % CI; s_w01t[k][j] = g_w01[idx]; }
    for (int idx = t; idx < L;    idx += 256) s_b01[idx] = g_b01[idx];
    for (int idx = t; idx < NN*NN; idx += 256) { int o = idx / NN, k = idx % NN; s_wcT[k*NN + o] = wc[idx]; }
    if (t < NN)   s_bc[t]  = bc[t];
    if (t < 2*NN) s_red[t] = 0.f;
    __syncthreads();

    const int ot = t >> 4;   // 0..12   (only t<208 active in y phase)
    const int lt = t & 15;   // 0..15
    float sAcc[4] = {0.f,0.f,0.f,0.f};
    float qAcc[4] = {0.f,0.f,0.f,0.f};

    for (int b = blockIdx.x; b < BATCH; b += gridDim.x) {
        const float* xb = x + (size_t)b * (CI*NN);
        for (int idx = t; idx < CI*NN; idx += 256) ((float*)s_x)[idx] = xb[idx];
        __syncthreads();

        // ---- h2 phase: thread computes (n, 4 j's), K = 14 ----
        for (int idx = t; idx < NN*32; idx += 256) {
            int n = idx >> 5, j0 = (idx & 31) << 2;
            float a0 = s_b01[j0], a1 = s_b01[j0+1], a2 = s_b01[j0+2], a3 = s_b01[j0+3];
            #pragma unroll
            for (int k = 0; k < CI; k++) {
                float xv = s_x[k][n];
                float4 w = *(const float4*)&s_w01t[k][j0];
                a0 = fmaf(xv, w.x, a0); a1 = fmaf(xv, w.y, a1);
                a2 = fmaf(xv, w.z, a2); a3 = fmaf(xv, w.w, a3);
            }
            float4 r = make_float4(fmaxf(a0,0.f), fmaxf(a1,0.f), fmaxf(a2,0.f), fmaxf(a3,0.f));
            *(float4*)&s_h2[n][j0] = r;
        }
        __syncthreads();

        // ---- y phase: 4o x 8l register tile, K = 52 ----
        if (t < 208) {
            float acc[4][8];
            #pragma unroll
            for (int i = 0; i < 4; i++) {
                float bv = s_bc[ot*4 + i];
                #pragma unroll
                for (int j = 0; j < 8; j++) acc[i][j] = bv;
            }
            #pragma unroll 4
            for (int k = 0; k < NN; k++) {
                float4 w  = *(const float4*)&s_wcT[k*NN + ot*4];
                float4 ha = *(const float4*)&s_h2[k][lt*8];
                float4 hb = *(const float4*)&s_h2[k][lt*8 + 4];
                float wv[4] = {w.x, w.y, w.z, w.w};
                float hv[8] = {ha.x, ha.y, ha.z, ha.w, hb.x, hb.y, hb.z, hb.w};
                #pragma unroll
                for (int i = 0; i < 4; i++)
                    #pragma unroll
                    for (int j = 0; j < 8; j++)
                        acc[i][j] = fmaf(wv[i], hv[j], acc[i][j]);
            }
            size_t base = ((size_t)b * NN + ot*4) * L + lt*8;
            #pragma unroll
            for (int i = 0; i < 4; i++) {
                *(float4*)&g_y[base + (size_t)i*L]     = make_float4(acc[i][0], acc[i][1], acc[i][2], acc[i][3]);
                *(float4*)&g_y[base + (size_t)i*L + 4] = make_float4(acc[i][4], acc[i][5], acc[i][6], acc[i][7]);
                #pragma unroll
                for (int j = 0; j < 8; j++) { sAcc[i] += acc[i][j]; qAcc[i] += acc[i][j]*acc[i][j]; }
            }
        }
        __syncthreads();
    }

    if (t < 208) {
        #pragma unroll
        for (int i = 0; i < 4; i++) {
            atomicAdd(&s_red[ot*4 + i],      sAcc[i]);
            atomicAdd(&s_red[NN + ot*4 + i], qAcc[i]);
        }
    }
    __syncthreads();
    if (t < NN) { atomicAdd(&g_sum1[t], s_red[t]); atomicAdd(&g_sq1[t], s_red[NN + t]); }
}

// ---------------------------------------------------------------------------
// BN coefficient kernels (fold batch stats into affine a*x + b)
// ---------------------------------------------------------------------------
__global__ void bn1_kernel(const float* __restrict__ g1, const float* __restrict__ be1) {
    int t = threadIdx.x;
    if (t < NN) {
        float n   = (float)BATCH * (float)L;
        float mu  = g_sum1[t] / n;
        float var = g_sq1[t] / n - mu*mu;
        float a   = g1[t] * rsqrtf(var + 1e-5f);
        g_a1[t]  = a;
        g_bb1[t] = be1[t] - mu * a;
    }
}

__global__ void bn2_kernel(const float* __restrict__ g2, const float* __restrict__ be2) {
    int t = threadIdx.x;
    if (t < H1C) {
        float n   = (float)BATCH;
        float mu  = g_sum2[t] / n;
        float var = g_sq2[t] / n - mu*mu;
        float a   = g2[t] * rsqrtf(var + 1e-5f);
        g_a2[t]  = a;
        g_bb2[t] = be2[t] - mu * a;
    }
}

// ---------------------------------------------------------------------------
// kernel C:  f = relu(a1*y + bb1) @ wf1.T + bf1   (M=32768, N=64, K=6656)
//            + accumulate per-column sum / sumsq for BN2
// ---------------------------------------------------------------------------
__global__ void __launch_bounds__(256, 2) kernelC(const float* __restrict__ wf1,
                                                  const float* __restrict__ bf1) {
    __shared__ __align__(16) float s_A[32][260];   // [k][row], padded
    __shared__ __align__(16) float s_B[32][64];    // [k][j]
    __shared__ float s_a1[NN], s_bb1[NN];
    __shared__ float s_cs[H1C], s_cq[H1C];

    int t = threadIdx.x;
    if (t < NN)  { s_a1[t] = g_a1[t]; s_bb1[t] = g_bb1[t]; }
    if (t < H1C) { s_cs[t] = 0.f; s_cq[t] = 0.f; }
    __syncthreads();

    const int tx = t & 7;    // col group: cols tx*8..tx*8+7
    const int ty = t >> 3;   // row group: rows ty*8..ty*8+7
    const int row0 = blockIdx.x * 256;
    float acc[8][8];
    #pragma unroll
    for (int i = 0; i < 8; i++)
        #pragma unroll
        for (int j = 0; j < 8; j++) acc[i][j] = 0.f;

    const float* Ab = g_y + (size_t)row0 * KFLAT;
    for (int k0 = 0; k0 < KFLAT; k0 += 32) {
        int   o  = k0 >> 7;                // channel constant within the 32-k tile
        float av = s_a1[o], bv = s_bb1[o];
        #pragma unroll
        for (int p = 0; p < 8; p++) {
            int r = ty + p*32;
            float4 v = *(const float4*)(Ab + (size_t)r*KFLAT + k0 + tx*4);
            s_A[tx*4+0][r] = fmaxf(fmaf(av, v.x, bv), 0.f);
            s_A[tx*4+1][r] = fmaxf(fmaf(av, v.y, bv), 0.f);
            s_A[tx*4+2][r] = fmaxf(fmaf(av, v.z, bv), 0.f);
            s_A[tx*4+3][r] = fmaxf(fmaf(av, v.w, bv), 0.f);
        }
        #pragma unroll
        for (int q = 0; q < 2; q++) {
            int idx4 = t + q*256;
            int j = idx4 >> 3, kq = (idx4 & 7) * 4;
            float4 v = *(const float4*)(wf1 + (size_t)j*KFLAT + k0 + kq);
            s_B[kq+0][j] = v.x; s_B[kq+1][j] = v.y; s_B[kq+2][j] = v.z; s_B[kq+3][j] = v.w;
        }
        __syncthreads();
        #pragma unroll
        for (int k = 0; k < 32; k++) {
            float4 a0  = *(const float4*)&s_A[k][ty*8];
            float4 a1f = *(const float4*)&s_A[k][ty*8 + 4];
            float4 b0  = *(const float4*)&s_B[k][tx*8];
            float4 b1f = *(const float4*)&s_B[k][tx*8 + 4];
            float ar[8] = {a0.x,a0.y,a0.z,a0.w,a1f.x,a1f.y,a1f.z,a1f.w};
            float br[8] = {b0.x,b0.y,b0.z,b0.w,b1f.x,b1f.y,b1f.z,b1f.w};
            #pragma unroll
            for (int i = 0; i < 8; i++)
                #pragma unroll
                for (int j = 0; j < 8; j++)
                    acc[i][j] = fmaf(ar[i], br[j], acc[i][j]);
        }
        __syncthreads();
    }

    float bfv[8];
    #pragma unroll
    for (int j = 0; j < 8; j++) bfv[j] = bf1[tx*8 + j];
    float cs[8], cq[8];
    #pragma unroll
    for (int j = 0; j < 8; j++) { cs[j] = 0.f; cq[j] = 0.f; }
    #pragma unroll
    for (int i = 0; i < 8; i++) {
        int r = row0 + ty*8 + i;
        float vv[8];
        #pragma unroll
        for (int j = 0; j < 8; j++) { vv[j] = acc[i][j] + bfv[j]; cs[j] += vv[j]; cq[j] += vv[j]*vv[j]; }
        *(float4*)&g_f[(size_t)r*H1C + tx*8]     = make_float4(vv[0], vv[1], vv[2], vv[3]);
        *(float4*)&g_f[(size_t)r*H1C + tx*8 + 4] = make_float4(vv[4], vv[5], vv[6], vv[7]);
    }
    #pragma unroll
    for (int j = 0; j < 8; j++) {
        atomicAdd(&s_cs[tx*8 + j], cs[j]);
        atomicAdd(&s_cq[tx*8 + j], cq[j]);
    }
    __syncthreads();
    if (t < H1C) { atomicAdd(&g_sum2[t], s_cs[t]); atomicAdd(&g_sq2[t], s_cq[t]); }
}

// ---------------------------------------------------------------------------
// kernel D:  out = relu(a2*f + bb2) @ wf2.T + bf2     [B,2]
// ---------------------------------------------------------------------------
__global__ void __launch_bounds__(256) kernelD(const float* __restrict__ wf2,
                                               const float* __restrict__ bf2,
                                               float* __restrict__ out) {
    __shared__ float s_f[64][65];
    __shared__ float s_w[2][H1C];
    __shared__ float s_a[H1C], s_b[H1C];
    int t = threadIdx.x;
    if (t < 2*H1C) s_w[t >> 6][t & 63] = wf2[t];
    if (t < H1C)  { s_a[t] = g_a2[t]; s_b[t] = g_bb2[t]; }
    int row0 = blockIdx.x * 64;
    #pragma unroll
    for (int p = 0; p < 16; p++) {
        int idx = t + p*256;
        int r = idx >> 6, c = idx & 63;
        s_f[r][c] = g_f[(size_t)(row0 + r)*H1C + c];
    }
    __syncthreads();
    if (t < 64) {
        float o0 = bf2[0], o1 = bf2[1];
        #pragma unroll
        for (int j = 0; j < H1C; j++) {
            float v = fmaxf(fmaf(s_a[j], s_f[t][j], s_b[j]), 0.f);
            o0 = fmaf(v, s_w[0][j], o0);
            o1 = fmaf(v, s_w[1][j], o1);
        }
        out[(size_t)(row0 + t)*2]     = o0;
        out[(size_t)(row0 + t)*2 + 1] = o1;
    }
}

// ---------------------------------------------------------------------------
extern "C" void kernel_launch(void* const* d_in, const int* in_sizes, int n_in,
                              void* d_out, int out_size) {
    const float* x   = (const float*)d_in[0];
    const float* w0  = (const float*)d_in[1];
    const float* b0  = (const float*)d_in[2];
    const float* w1  = (const float*)d_in[3];
    const float* b1  = (const float*)d_in[4];
    const float* wc  = (const float*)d_in[5];
    const float* bc  = (const float*)d_in[6];
    const float* g1  = (const float*)d_in[7];
    const float* be1 = (const float*)d_in[8];
    const float* wf1 = (const float*)d_in[9];
    const float* bf1 = (const float*)d_in[10];
    const float* g2  = (const float*)d_in[11];
    const float* be2 = (const float*)d_in[12];
    const float* wf2 = (const float*)d_in[13];
    const float* bf2 = (const float*)d_in[14];
    float* out = (float*)d_out;

    prep_kernel<<<1, 256>>>(w0, b0, w1, b1);
    kernelA<<<444, 256>>>(x, wc, bc);
    bn1_kernel<<<1, 64>>>(g1, be1);
    kernelC<<<BATCH/256, 256>>>(wf1, bf1);
    bn2_kernel<<<1, 64>>>(g2, be2);
    kernelD<<<BATCH/64, 256>>>(wf2, bf2, out);
}

// round 2
// speedup vs baseline: 1.4175x; 1.4175x over previous
#include <cuda_runtime.h>

#define BATCH 32768
#define CI 14
#define NN 52
#define H1C 64
#define L 128
#define KFLAT (NN*L)   // 6656
#define CLS 2

// ---- scratch (device globals: no allocation allowed) ----
__device__ float g_y[(size_t)BATCH * KFLAT];   // y_pre  [B,52,128]
__device__ float g_f[(size_t)BATCH * H1C];     // f      [B,64]
__device__ float g_w01[L * CI];                // folded w1@w0  [128,14]
__device__ float g_b01[L];
__device__ float g_sum1[NN], g_sq1[NN], g_a1[NN], g_bb1[NN];
__device__ float g_sum2[H1C], g_sq2[H1C], g_a2[H1C], g_bb2[H1C];

__device__ __forceinline__ unsigned f2tf(float f) {
    unsigned u;
    asm("cvt.rna.tf32.f32 %0, %1;" : "=r"(u) : "f"(f));
    return u;
}

__device__ __forceinline__ void mma_tf32(float c[4], const unsigned a[4], const unsigned b[2]) {
    asm volatile(
        "mma.sync.aligned.m16n8k8.row.col.f32.tf32.tf32.f32 "
        "{%0,%1,%2,%3}, {%4,%5,%6,%7}, {%8,%9}, {%0,%1,%2,%3};"
        : "+f"(c[0]), "+f"(c[1]), "+f"(c[2]), "+f"(c[3])
        : "r"(a[0]), "r"(a[1]), "r"(a[2]), "r"(a[3]), "r"(b[0]), "r"(b[1]));
}

// ---------------------------------------------------------------------------
// prep: fold the two linear GNN layers; zero stat accumulators
// ---------------------------------------------------------------------------
__global__ void prep_kernel(const float* __restrict__ w0, const float* __restrict__ b0,
                            const float* __restrict__ w1, const float* __restrict__ b1) {
    int t = threadIdx.x;
    if (t < NN)  { g_sum1[t] = 0.f; g_sq1[t] = 0.f; }
    if (t < H1C) { g_sum2[t] = 0.f; g_sq2[t] = 0.f; }
    for (int idx = t; idx < L * CI; idx += blockDim.x) {
        int j = idx / CI, k = idx % CI;
        float acc = 0.f;
        for (int i = 0; i < H1C; i++) acc += w1[j*H1C + i] * w0[i*CI + k];
        g_w01[idx] = acc;
    }
    if (t < L) {
        float acc = b1[t];
        for (int i = 0; i < H1C; i++) acc += w1[t*H1C + i] * b0[i];
        g_b01[t] = acc;
    }
}

// ---------------------------------------------------------------------------
// kernel A: per sample  h2 = relu(xt @ w01.T + b01)  [52,128]
//           y  = wc @ h2 + bc                        [52,128] -> g_y
//           accumulate per-channel sum / sumsq for BN1
// ---------------------------------------------------------------------------
__global__ void __launch_bounds__(256, 3) kernelA(const float* __restrict__ x,
                                                  const float* __restrict__ wc,
                                                  const float* __restrict__ bc) {
    __shared__ __align__(16) float s_w01t[CI][L];   // [k][j]
    __shared__ float s_b01[L];
    __shared__ __align__(16) float s_wcT[NN*NN];    // [k*52 + o]
    __shared__ float s_bc[NN];
    __shared__ float s_x[CI][NN];                   // [c][n]  (x natural layout)
    __shared__ __align__(16) float s_h2[NN][L];     // [n][l]
    __shared__ float s_red[2*NN];

    int t = threadIdx.x;
    for (int idx = t; idx < L*CI; idx += 256) { int j = idx / CI, k = idx % CI; s_w01t[k][j] = g_w01[idx]; }
    for (int idx = t; idx < L;    idx += 256) s_b01[idx] = g_b01[idx];
    for (int idx = t; idx < NN*NN; idx += 256) { int o = idx / NN, k = idx % NN; s_wcT[k*NN + o] = wc[idx]; }
    if (t < NN)   s_bc[t]  = bc[t];
    if (t < 2*NN) s_red[t] = 0.f;
    __syncthreads();

    const int ot = t >> 4;   // 0..12   (only t<208 active in y phase)
    const int lt = t & 15;   // 0..15
    float sAcc[4] = {0.f,0.f,0.f,0.f};
    float qAcc[4] = {0.f,0.f,0.f,0.f};

    for (int b = blockIdx.x; b < BATCH; b += gridDim.x) {
        const float* xb = x + (size_t)b * (CI*NN);
        for (int idx = t; idx < CI*NN; idx += 256) ((float*)s_x)[idx] = xb[idx];
        __syncthreads();

        // ---- h2 phase: thread computes (n, 4 j's), K = 14 ----
        for (int idx = t; idx < NN*32; idx += 256) {
            int n = idx >> 5, j0 = (idx & 31) << 2;
            float a0 = s_b01[j0], a1 = s_b01[j0+1], a2 = s_b01[j0+2], a3 = s_b01[j0+3];
            #pragma unroll
            for (int k = 0; k < CI; k++) {
                float xv = s_x[k][n];
                float4 w = *(const float4*)&s_w01t[k][j0];
                a0 = fmaf(xv, w.x, a0); a1 = fmaf(xv, w.y, a1);
                a2 = fmaf(xv, w.z, a2); a3 = fmaf(xv, w.w, a3);
            }
            float4 r = make_float4(fmaxf(a0,0.f), fmaxf(a1,0.f), fmaxf(a2,0.f), fmaxf(a3,0.f));
            *(float4*)&s_h2[n][j0] = r;
        }
        __syncthreads();

        // ---- y phase: 4o x 8l register tile, K = 52 ----
        if (t < 208) {
            float acc[4][8];
            #pragma unroll
            for (int i = 0; i < 4; i++) {
                float bv = s_bc[ot*4 + i];
                #pragma unroll
                for (int j = 0; j < 8; j++) acc[i][j] = bv;
            }
            #pragma unroll 4
            for (int k = 0; k < NN; k++) {
                float4 w  = *(const float4*)&s_wcT[k*NN + ot*4];
                float4 ha = *(const float4*)&s_h2[k][lt*8];
                float4 hb = *(const float4*)&s_h2[k][lt*8 + 4];
                float wv[4] = {w.x, w.y, w.z, w.w};
                float hv[8] = {ha.x, ha.y, ha.z, ha.w, hb.x, hb.y, hb.z, hb.w};
                #pragma unroll
                for (int i = 0; i < 4; i++)
                    #pragma unroll
                    for (int j = 0; j < 8; j++)
                        acc[i][j] = fmaf(wv[i], hv[j], acc[i][j]);
            }
            size_t base = ((size_t)b * NN + ot*4) * L + lt*8;
            #pragma unroll
            for (int i = 0; i < 4; i++) {
                *(float4*)&g_y[base + (size_t)i*L]     = make_float4(acc[i][0], acc[i][1], acc[i][2], acc[i][3]);
                *(float4*)&g_y[base + (size_t)i*L + 4] = make_float4(acc[i][4], acc[i][5], acc[i][6], acc[i][7]);
                #pragma unroll
                for (int j = 0; j < 8; j++) { sAcc[i] += acc[i][j]; qAcc[i] += acc[i][j]*acc[i][j]; }
            }
        }
        __syncthreads();
    }

    if (t < 208) {
        #pragma unroll
        for (int i = 0; i < 4; i++) {
            atomicAdd(&s_red[ot*4 + i],      sAcc[i]);
            atomicAdd(&s_red[NN + ot*4 + i], qAcc[i]);
        }
    }
    __syncthreads();
    if (t < NN) { atomicAdd(&g_sum1[t], s_red[t]); atomicAdd(&g_sq1[t], s_red[NN + t]); }
}

// ---------------------------------------------------------------------------
// BN coefficient kernels (fold batch stats into affine a*x + b)
// ---------------------------------------------------------------------------
__global__ void bn1_kernel(const float* __restrict__ g1, const float* __restrict__ be1) {
    int t = threadIdx.x;
    if (t < NN) {
        float n   = (float)BATCH * (float)L;
        float mu  = g_sum1[t] / n;
        float var = g_sq1[t] / n - mu*mu;
        float a   = g1[t] * rsqrtf(var + 1e-5f);
        g_a1[t]  = a;
        g_bb1[t] = be1[t] - mu * a;
    }
}

__global__ void bn2_kernel(const float* __restrict__ g2, const float* __restrict__ be2) {
    int t = threadIdx.x;
    if (t < H1C) {
        float n   = (float)BATCH;
        float mu  = g_sum2[t] / n;
        float var = g_sq2[t] / n - mu*mu;
        float a   = g2[t] * rsqrtf(var + 1e-5f);
        g_a2[t]  = a;
        g_bb2[t] = be2[t] - mu * a;
    }
}

// ---------------------------------------------------------------------------
// kernel C (tf32 tensor-core):
//   f = relu(a1*y + bb1) @ wf1.T + bf1    (M=32768, N=64, K=6656)
//   + per-column sum / sumsq for BN2
// Tile: 128 rows x 64 cols, K-step 32. 8 warps as 4(M) x 2(N), warp = 32x32.
// smem layouts (stride 36 words): A[row][k], B[n][k] -> both STS.128 staging
// and the 4xLDS.32 fragment gathers are bank-conflict-free.
// ---------------------------------------------------------------------------
#define KT 32
#define NKT (KFLAT/KT)   // 208

__global__ void __launch_bounds__(256, 2) kernelC(const float* __restrict__ wf1,
                                                  const float* __restrict__ bf1) {
    __shared__ __align__(16) unsigned s_A[128*36];
    __shared__ __align__(16) unsigned s_B[64*36];
    __shared__ float s_a1s[NN], s_bb1s[NN];
    __shared__ float s_cs[H1C], s_cq[H1C];

    const int t = threadIdx.x;
    if (t < NN)  { s_a1s[t] = g_a1[t]; s_bb1s[t] = g_bb1[t]; }
    if (t < H1C) { s_cs[t] = 0.f; s_cq[t] = 0.f; }
    __syncthreads();

    const int row0 = blockIdx.x * 128;
    const int tx = t & 7, ty = t >> 3;          // staging: 8 k-chunks x 32 rows
    const int lane = t & 31, w = t >> 5;
    const int wm = w & 3, wn = w >> 2;
    const int m0 = wm * 32, n0 = wn * 32;
    const int lq = lane >> 2, lr = lane & 3;    // groupID, threadID_in_group

    const float* Ab = g_y + (size_t)row0 * KFLAT;

    float4 pa[4];
    float4 pb[2];

    // ---- stage tile 0 ----
    {
        #pragma unroll
        for (int p = 0; p < 4; p++)
            pa[p] = *(const float4*)(Ab + (size_t)(ty + p*32)*KFLAT + tx*4);
        #pragma unroll
        for (int q = 0; q < 2; q++) {
            int lin = t + q*256;
            pb[q] = *(const float4*)(wf1 + (size_t)(lin >> 3)*KFLAT + (lin & 7)*4);
        }
        float av = s_a1s[0], bv = s_bb1s[0];
        #pragma unroll
        for (int p = 0; p < 4; p++) {
            int r = ty + p*32;
            uint4 u;
            u.x = f2tf(fmaxf(fmaf(av, pa[p].x, bv), 0.f));
            u.y = f2tf(fmaxf(fmaf(av, pa[p].y, bv), 0.f));
            u.z = f2tf(fmaxf(fmaf(av, pa[p].z, bv), 0.f));
            u.w = f2tf(fmaxf(fmaf(av, pa[p].w, bv), 0.f));
            *(uint4*)&s_A[r*36 + tx*4] = u;
        }
        #pragma unroll
        for (int q = 0; q < 2; q++) {
            int lin = t + q*256;
            int j = lin >> 3, kk = (lin & 7)*4;
            uint4 u;
            u.x = f2tf(pb[q].x); u.y = f2tf(pb[q].y);
            u.z = f2tf(pb[q].z); u.w = f2tf(pb[q].w);
            *(uint4*)&s_B[j*36 + kk] = u;
        }
    }
    __syncthreads();

    float c[2][4][4];
    #pragma unroll
    for (int m = 0; m < 2; m++)
        #pragma unroll
        for (int nt = 0; nt < 4; nt++)
            #pragma unroll
            for (int e = 0; e < 4; e++) c[m][nt][e] = 0.f;

    for (int kt = 0; kt < NKT; kt++) {
        const int k0n = (kt + 1) * KT;
        if (kt < NKT - 1) {
            #pragma unroll
            for (int p = 0; p < 4; p++)
                pa[p] = *(const float4*)(Ab + (size_t)(ty + p*32)*KFLAT + k0n + tx*4);
            #pragma unroll
            for (int q = 0; q < 2; q++) {
                int lin = t + q*256;
                pb[q] = *(const float4*)(wf1 + (size_t)(lin >> 3)*KFLAT + k0n + (lin & 7)*4);
            }
        }

        // ---- compute on resident tile ----
        #pragma unroll
        for (int kc = 0; kc < 4; kc++) {
            const int kb = kc*8 + lr;
            unsigned a[2][4], b[4][2];
            #pragma unroll
            for (int m = 0; m < 2; m++) {
                int r = m0 + m*16 + lq;
                a[m][0] = s_A[r*36 + kb];
                a[m][1] = s_A[(r+8)*36 + kb];
                a[m][2] = s_A[r*36 + kb + 4];
                a[m][3] = s_A[(r+8)*36 + kb + 4];
            }
            #pragma unroll
            for (int nt = 0; nt < 4; nt++) {
                int n = n0 + nt*8 + lq;
                b[nt][0] = s_B[n*36 + kb];
                b[nt][1] = s_B[n*36 + kb + 4];
            }
            #pragma unroll
            for (int m = 0; m < 2; m++)
                #pragma unroll
                for (int nt = 0; nt < 4; nt++)
                    mma_tf32(c[m][nt], a[m], b[nt]);
        }
        __syncthreads();

        if (kt < NKT - 1) {
            float av = s_a1s[k0n >> 7], bv = s_bb1s[k0n >> 7];
            #pragma unroll
            for (int p = 0; p < 4; p++) {
                int r = ty + p*32;
                uint4 u;
                u.x = f2tf(fmaxf(fmaf(av, pa[p].x, bv), 0.f));
                u.y = f2tf(fmaxf(fmaf(av, pa[p].y, bv), 0.f));
                u.z = f2tf(fmaxf(fmaf(av, pa[p].z, bv), 0.f));
                u.w = f2tf(fmaxf(fmaf(av, pa[p].w, bv), 0.f));
                *(uint4*)&s_A[r*36 + tx*4] = u;
            }
            #pragma unroll
            for (int q = 0; q < 2; q++) {
                int lin = t + q*256;
                int j = lin >> 3, kk = (lin & 7)*4;
                uint4 u;
                u.x = f2tf(pb[q].x); u.y = f2tf(pb[q].y);
                u.z = f2tf(pb[q].z); u.w = f2tf(pb[q].w);
                *(uint4*)&s_B[j*36 + kk] = u;
            }
            __syncthreads();
        }
    }

    // ---- epilogue: bias, store f, BN2 stats ----
    float bias[4][2];
    #pragma unroll
    for (int nt = 0; nt < 4; nt++) {
        bias[nt][0] = bf1[n0 + nt*8 + lr*2];
        bias[nt][1] = bf1[n0 + nt*8 + lr*2 + 1];
    }
    float cs[4][2], cq[4][2];
    #pragma unroll
    for (int nt = 0; nt < 4; nt++) { cs[nt][0]=cs[nt][1]=0.f; cq[nt][0]=cq[nt][1]=0.f; }

    #pragma unroll
    for (int m = 0; m < 2; m++) {
        #pragma unroll
        for (int h = 0; h < 2; h++) {
            int row = row0 + m0 + m*16 + lq + h*8;
            #pragma unroll
            for (int nt = 0; nt < 4; nt++) {
                float v0 = c[m][nt][h*2]     + bias[nt][0];
                float v1 = c[m][nt][h*2 + 1] + bias[nt][1];
                *(float2*)&g_f[(size_t)row*H1C + n0 + nt*8 + lr*2] = make_float2(v0, v1);
                cs[nt][0] += v0; cq[nt][0] += v0*v0;
                cs[nt][1] += v1; cq[nt][1] += v1*v1;
            }
        }
    }
    #pragma unroll
    for (int nt = 0; nt < 4; nt++) {
        int col = n0 + nt*8 + lr*2;
        atomicAdd(&s_cs[col],   cs[nt][0]);
        atomicAdd(&s_cq[col],   cq[nt][0]);
        atomicAdd(&s_cs[col+1], cs[nt][1]);
        atomicAdd(&s_cq[col+1], cq[nt][1]);
    }
    __syncthreads();
    if (t < H1C) { atomicAdd(&g_sum2[t], s_cs[t]); atomicAdd(&g_sq2[t], s_cq[t]); }
}

// ---------------------------------------------------------------------------
// kernel D:  out = relu(a2*f + bb2) @ wf2.T + bf2     [B,2]
// ---------------------------------------------------------------------------
__global__ void __launch_bounds__(256) kernelD(const float* __restrict__ wf2,
                                               const float* __restrict__ bf2,
                                               float* __restrict__ out) {
    __shared__ float s_f[64][65];
    __shared__ float s_w[2][H1C];
    __shared__ float s_a[H1C], s_b[H1C];
    int t = threadIdx.x;
    if (t < 2*H1C) s_w[t >> 6][t & 63] = wf2[t];
    if (t < H1C)  { s_a[t] = g_a2[t]; s_b[t] = g_bb2[t]; }
    int row0 = blockIdx.x * 64;
    #pragma unroll
    for (int p = 0; p < 16; p++) {
        int idx = t + p*256;
        int r = idx >> 6, c = idx & 63;
        s_f[r][c] = g_f[(size_t)(row0 + r)*H1C + c];
    }
    __syncthreads();
    if (t < 64) {
        float o0 = bf2[0], o1 = bf2[1];
        #pragma unroll
        for (int j = 0; j < H1C; j++) {
            float v = fmaxf(fmaf(s_a[j], s_f[t][j], s_b[j]), 0.f);
            o0 = fmaf(v, s_w[0][j], o0);
            o1 = fmaf(v, s_w[1][j], o1);
        }
        out[(size_t)(row0 + t)*2]     = o0;
        out[(size_t)(row0 + t)*2 + 1] = o1;
    }
}

// ---------------------------------------------------------------------------
extern "C" void kernel_launch(void* const* d_in, const int* in_sizes, int n_in,
                              void* d_out, int out_size) {
    const float* x   = (const float*)d_in[0];
    const float* w0  = (const float*)d_in[1];
    const float* b0  = (const float*)d_in[2];
    const float* w1  = (const float*)d_in[3];
    const float* b1  = (const float*)d_in[4];
    const float* wc  = (const float*)d_in[5];
    const float* bc  = (const float*)d_in[6];
    const float* g1  = (const float*)d_in[7];
    const float* be1 = (const float*)d_in[8];
    const float* wf1 = (const float*)d_in[9];
    const float* bf1 = (const float*)d_in[10];
    const float* g2  = (const float*)d_in[11];
    const float* be2 = (const float*)d_in[12];
    const float* wf2 = (const float*)d_in[13];
    const float* bf2 = (const float*)d_in[14];
    float* out = (float*)d_out;

    prep_kernel<<<1, 256>>>(w0, b0, w1, b1);
    kernelA<<<444, 256>>>(x, wc, bc);
    bn1_kernel<<<1, 64>>>(g1, be1);
    kernelC<<<BATCH/128, 256>>>(wf1, bf1);
    bn2_kernel<<<1, 64>>>(g2, be2);
    kernelD<<<BATCH/64, 256>>>(wf2, bf2, out);
}